// round 6
// baseline (speedup 1.0000x reference)
#include <cuda_runtime.h>

// Problem constants
#define NSEG   7
#define NSUBS  4
#define NEVAL  (NSEG*NSUBS*3)   // 84 hypernet evaluations (seg, sub, stage)
#define NROW   128              // WIDTH
#define ROWF   36               // floats per table row: Wdup[16], Udup[16], B,B,-c,-c
#define TABF   (NROW*ROWF)      // 4608 floats = 18KB per table
#define NPTS   65536
#define LPOFF  (8*NPTS*8)       // zt occupies first 8*N*8 floats, then logp 8*N

__device__ float g_tab[NEVAL * TABF];   // 1.548 MB precomputed hypernet tables

typedef unsigned long long u64;

// ---------------- f32x2 packed helpers ----------------
static __device__ __forceinline__ u64 pk2(float a, float b){
    u64 r; asm("mov.b64 %0, {%1, %2};" : "=l"(r) : "f"(a), "f"(b)); return r;
}
static __device__ __forceinline__ void upk2(u64 v, float& a, float& b){
    asm("mov.b64 {%0, %1}, %2;" : "=f"(a), "=f"(b) : "l"(v));
}
static __device__ __forceinline__ u64 ffma2(u64 a, u64 b, u64 c){
    u64 d; asm("fma.rn.f32x2 %0, %1, %2, %3;" : "=l"(d) : "l"(a), "l"(b), "l"(c)); return d;
}
static __device__ __forceinline__ u64 fadd2(u64 a, u64 b){
    u64 d; asm("add.rn.f32x2 %0, %1, %2;" : "=l"(d) : "l"(a), "l"(b)); return d;
}
static __device__ __forceinline__ u64 fmul2(u64 a, u64 b){
    u64 d; asm("mul.rn.f32x2 %0, %1, %2;" : "=l"(d) : "l"(a), "l"(b)); return d;
}

static __device__ __forceinline__ float tanh_fast(float x){
    // 1 - 2/(1+e^{2x}); handles +/-inf overflow correctly (-> +/-1)
    float e = __expf(2.0f * x);
    return 1.0f - __fdividef(2.0f, 1.0f + e);
}

// ---------------- Hypernetwork: precompute (W, B, U/128, -c) tables ----------------
// eval e -> seg = e/12, sub = (e%12)/3, stage = e%3 (0: t, 1: t+dt/2, 2: t+dt)
__global__ void hyper_kernel(const float* __restrict__ ts,
    const float* __restrict__ w1, const float* __restrict__ b1,
    const float* __restrict__ w2, const float* __restrict__ b2,
    const float* __restrict__ w3, const float* __restrict__ b3)
{
    __shared__ float h1s[64], h2s[64];
    const int e = blockIdx.x;
    const int tid = threadIdx.x;        // 128 threads
    const int seg = e / 12, r = e % 12, sub = r / 3, st = r % 3;

    float t0 = ts[seg], t1 = ts[seg+1];
    float dt = (t1 - t0) / 4.0f;
    float t = t0;
    for (int k = 0; k < sub; k++) t += dt;   // replicate reference's iterative t accumulation
    if      (st == 1) t += dt * 0.5f;
    else if (st == 2) t += dt;

    if (tid < 64) h1s[tid] = tanhf(w1[tid] * t + b1[tid]);
    __syncthreads();
    if (tid < 64) {
        float acc = b2[tid];
        const float* row = w2 + tid * 64;
        #pragma unroll 8
        for (int k = 0; k < 64; k++) acc += row[k] * h1s[k];
        h2s[tid] = tanhf(acc);
    }
    __syncthreads();

    const int i = tid;                  // output row 0..127
    float W[8], U[8];
    #pragma unroll
    for (int d = 0; d < 8; d++) {
        int mW = i*8 + d, mU = 1024 + i*8 + d, mG = 2048 + i*8 + d;
        float aw = b3[mW], au = b3[mU], ag = b3[mG];
        const float4* rw = (const float4*)(w3 + mW*64);
        const float4* ru = (const float4*)(w3 + mU*64);
        const float4* rg = (const float4*)(w3 + mG*64);
        #pragma unroll 4
        for (int k = 0; k < 16; k++) {
            float4 vw = rw[k], vu = ru[k], vg = rg[k];
            float hA = h2s[4*k], hB = h2s[4*k+1], hC = h2s[4*k+2], hD = h2s[4*k+3];
            aw += vw.x*hA + vw.y*hB + vw.z*hC + vw.w*hD;
            au += vu.x*hA + vu.y*hB + vu.z*hC + vu.w*hD;
            ag += vg.x*hA + vg.y*hB + vg.z*hC + vg.w*hD;
        }
        float sg = 1.0f / (1.0f + expf(-ag));
        W[d] = aw;
        U[d] = au * sg * (1.0f/128.0f);   // fold /WIDTH into U
    }
    int mB = 3072 + i;
    float ab = b3[mB];
    {
        const float4* rb = (const float4*)(w3 + mB*64);
        #pragma unroll 4
        for (int k = 0; k < 16; k++) {
            float4 v = rb[k];
            ab += v.x*h2s[4*k] + v.y*h2s[4*k+1] + v.z*h2s[4*k+2] + v.w*h2s[4*k+3];
        }
    }
    float c = 0.0f;                       // trace coefficient: sum_d W_d * (U_d/128)
    #pragma unroll
    for (int d = 0; d < 8; d++) c += W[d]*U[d];

    float* o = g_tab + (size_t)e*TABF + i*ROWF;
    #pragma unroll
    for (int d = 0; d < 8; d++) { o[2*d]    = W[d]; o[2*d+1]    = W[d]; }
    #pragma unroll
    for (int d = 0; d < 8; d++) { o[16+2*d] = U[d]; o[16+2*d+1] = U[d]; }
    o[32] = ab; o[33] = ab; o[34] = -c; o[35] = -c;
}

// ---------------- RHS: dz and trace for 2 samples packed per thread ----------------
static __device__ __forceinline__ void rhs_eval(const float* __restrict__ tab,
                                                const u64 z[8], u64 dz[8], u64& tr)
{
    #pragma unroll
    for (int d = 0; d < 8; d++) dz[d] = 0ULL;
    tr = 0ULL;
    const u64 M1 = 0xBF800000BF800000ULL;     // (-1.0f, -1.0f)

    #pragma unroll 2
    for (int i = 0; i < NROW; i++) {
        const float4* r4 = (const float4*)(tab + i*ROWF);
        float4 wa = r4[0], wb = r4[1], wc = r4[2], wd = r4[3];  // W dup pairs
        float4 ua = r4[4], ub = r4[5], uc = r4[6], ud = r4[7];  // U dup pairs
        float4 bc = r4[8];                                      // B,B,-c,-c

        u64 sa = ffma2(pk2(wa.x,wa.y), z[0], pk2(bc.x,bc.y));
        u64 sb = fmul2(pk2(wa.z,wa.w), z[1]);
        sa = ffma2(pk2(wb.x,wb.y), z[2], sa);
        sb = ffma2(pk2(wb.z,wb.w), z[3], sb);
        sa = ffma2(pk2(wc.x,wc.y), z[4], sa);
        sb = ffma2(pk2(wc.z,wc.w), z[5], sb);
        sa = ffma2(pk2(wd.x,wd.y), z[6], sa);
        sb = ffma2(pk2(wd.z,wd.w), z[7], sb);
        u64 s = fadd2(sa, sb);

        float s0, s1; upk2(s, s0, s1);
        u64 h = pk2(tanh_fast(s0), tanh_fast(s1));

        dz[0] = ffma2(h, pk2(ua.x,ua.y), dz[0]);
        dz[1] = ffma2(h, pk2(ua.z,ua.w), dz[1]);
        dz[2] = ffma2(h, pk2(ub.x,ub.y), dz[2]);
        dz[3] = ffma2(h, pk2(ub.z,ub.w), dz[3]);
        dz[4] = ffma2(h, pk2(uc.x,uc.y), dz[4]);
        dz[5] = ffma2(h, pk2(uc.z,uc.w), dz[5]);
        dz[6] = ffma2(h, pk2(ud.x,ud.y), dz[6]);
        dz[7] = ffma2(h, pk2(ud.z,ud.w), dz[7]);

        u64 g = ffma2(h, h, M1);                 // h^2 - 1
        tr = ffma2(g, pk2(bc.z,bc.w), tr);       // += (1-h^2)*c   (trace)
    }
}

// ---------------- Main integration kernel: 2 samples per thread ----------------
__global__ void __launch_bounds__(128) cnf_main(
    const float* __restrict__ ts, const float* __restrict__ z0,
    const float* __restrict__ lp0, float* __restrict__ out)
{
    __shared__ float stab[2*TABF];          // 36 KB: [E | M] staged tables
    float* sE = stab;
    float* sM = stab + TABF;
    const int tid = threadIdx.x;
    const int n0 = (blockIdx.x * 128 + tid) * 2;

    // load z for samples n0, n0+1; pack across samples: z[d] = (z_{n0,d}, z_{n0+1,d})
    const float4* zv = (const float4*)(z0 + (size_t)n0*8);
    float4 p0 = zv[0], p1 = zv[1], p2 = zv[2], p3 = zv[3];
    u64 z[8];
    z[0]=pk2(p0.x,p2.x); z[1]=pk2(p0.y,p2.y); z[2]=pk2(p0.z,p2.z); z[3]=pk2(p0.w,p2.w);
    z[4]=pk2(p1.x,p3.x); z[5]=pk2(p1.y,p3.y); z[6]=pk2(p1.z,p3.z); z[7]=pk2(p1.w,p3.w);

    float lpa = lp0[n0], lpb = lp0[n0+1];
    u64 lp = pk2(lpa, lpb);

    // t = ts[0] output slice
    {
        float4* ov = (float4*)(out + (size_t)n0*8);
        ov[0]=p0; ov[1]=p1; ov[2]=p2; ov[3]=p3;
        out[LPOFF + n0]     = lpa;
        out[LPOFF + n0 + 1] = lpb;
    }

    const u64 M_TWO = pk2(2.0f, 2.0f);

    for (int seg = 0; seg < NSEG; seg++) {
        float t0 = ts[seg], t1 = ts[seg+1];
        float dt  = (t1 - t0) / 4.0f;
        float hdt = dt * 0.5f;
        float dt6 = dt / 6.0f;
        u64 DT = pk2(dt,dt), HDT = pk2(hdt,hdt), DT6 = pk2(dt6,dt6), NDT6 = pk2(-dt6,-dt6);

        for (int sub = 0; sub < NSUBS; sub++) {
            const int ev = (seg*NSUBS + sub)*3;

            // stage E <- stage0 table, M <- stage1 (midpoint) table
            __syncthreads();
            {
                const float4* srcE = (const float4*)(g_tab + (size_t)ev*TABF);
                const float4* srcM = (const float4*)(g_tab + (size_t)(ev+1)*TABF);
                float4* dE = (float4*)sE; float4* dM = (float4*)sM;
                for (int j = tid; j < TABF/4; j += 128) { dE[j] = srcE[j]; dM[j] = srcM[j]; }
            }
            __syncthreads();

            u64 kd[8], acc[8], zt[8], tr, trs;

            rhs_eval(sE, z, kd, tr);                     // k1 @ t
            trs = tr;
            #pragma unroll
            for (int d = 0; d < 8; d++) { acc[d] = kd[d]; zt[d] = ffma2(HDT, kd[d], z[d]); }

            rhs_eval(sM, zt, kd, tr);                    // k2 @ t+dt/2
            trs = ffma2(M_TWO, tr, trs);
            #pragma unroll
            for (int d = 0; d < 8; d++) { acc[d] = ffma2(M_TWO, kd[d], acc[d]); zt[d] = ffma2(HDT, kd[d], z[d]); }

            rhs_eval(sM, zt, kd, tr);                    // k3 @ t+dt/2
            trs = ffma2(M_TWO, tr, trs);
            #pragma unroll
            for (int d = 0; d < 8; d++) { acc[d] = ffma2(M_TWO, kd[d], acc[d]); zt[d] = ffma2(DT, kd[d], z[d]); }

            // restage E <- stage2 (t+dt) table for k4
            __syncthreads();
            {
                const float4* srcE = (const float4*)(g_tab + (size_t)(ev+2)*TABF);
                float4* dE = (float4*)sE;
                for (int j = tid; j < TABF/4; j += 128) dE[j] = srcE[j];
            }
            __syncthreads();

            rhs_eval(sE, zt, kd, tr);                    // k4 @ t+dt
            trs = fadd2(trs, tr);
            #pragma unroll
            for (int d = 0; d < 8; d++) { acc[d] = fadd2(acc[d], kd[d]); z[d] = ffma2(DT6, acc[d], z[d]); }
            lp = ffma2(NDT6, trs, lp);                   // lp += dt/6 * (-(tr1+2tr2+2tr3+tr4))
        }

        // write slice seg+1
        float za[8], zb[8];
        #pragma unroll
        for (int d = 0; d < 8; d++) upk2(z[d], za[d], zb[d]);
        float4* ov = (float4*)(out + (size_t)(seg+1)*NPTS*8 + (size_t)n0*8);
        ov[0] = make_float4(za[0], za[1], za[2], za[3]);
        ov[1] = make_float4(za[4], za[5], za[6], za[7]);
        ov[2] = make_float4(zb[0], zb[1], zb[2], zb[3]);
        ov[3] = make_float4(zb[4], zb[5], zb[6], zb[7]);
        float la, lb; upk2(lp, la, lb);
        out[LPOFF + (size_t)(seg+1)*NPTS + n0]     = la;
        out[LPOFF + (size_t)(seg+1)*NPTS + n0 + 1] = lb;
    }
}

extern "C" void kernel_launch(void* const* d_in, const int* in_sizes, int n_in,
                              void* d_out, int out_size) {
    const float* ts  = (const float*)d_in[0];
    const float* z0  = (const float*)d_in[1];
    const float* lp0 = (const float*)d_in[2];
    const float* w1  = (const float*)d_in[3];
    const float* b1  = (const float*)d_in[4];
    const float* w2  = (const float*)d_in[5];
    const float* b2  = (const float*)d_in[6];
    const float* w3  = (const float*)d_in[7];
    const float* b3  = (const float*)d_in[8];
    float* out = (float*)d_out;

    hyper_kernel<<<NEVAL, 128>>>(ts, w1, b1, w2, b2, w3, b3);
    cnf_main<<<NPTS/256, 128>>>(ts, z0, lp0, out);
}

// round 7
// speedup vs baseline: 1.2410x; 1.2410x over previous
#include <cuda_runtime.h>

// Problem constants
#define NSEG   7
#define NSUBS  4
#define NEVAL  (NSEG*NSUBS*3)   // 84 hypernet evaluations (seg, sub, stage)
#define NROW   128              // WIDTH
#define ROWF   20               // floats per table row: Wpair[8], Upair[8], B, 0, -c, -c
#define TABF   (NROW*ROWF)      // 2560 floats = 10KB per table
#define NPTS   65536
#define LPOFF  (8*NPTS*8)       // zt occupies first 8*N*8 floats, then logp 8*N

__device__ float g_tab[NEVAL * TABF];   // 860 KB precomputed hypernet tables

typedef unsigned long long u64;

// ---------------- f32x2 packed helpers ----------------
static __device__ __forceinline__ u64 pk2(float a, float b){
    u64 r; asm("mov.b64 %0, {%1, %2};" : "=l"(r) : "f"(a), "f"(b)); return r;
}
static __device__ __forceinline__ void upk2(u64 v, float& a, float& b){
    asm("mov.b64 {%0, %1}, %2;" : "=f"(a), "=f"(b) : "l"(v));
}
static __device__ __forceinline__ u64 ffma2(u64 a, u64 b, u64 c){
    u64 d; asm("fma.rn.f32x2 %0, %1, %2, %3;" : "=l"(d) : "l"(a), "l"(b), "l"(c)); return d;
}
static __device__ __forceinline__ u64 fadd2(u64 a, u64 b){
    u64 d; asm("add.rn.f32x2 %0, %1, %2;" : "=l"(d) : "l"(a), "l"(b)); return d;
}
static __device__ __forceinline__ u64 fmul2(u64 a, u64 b){
    u64 d; asm("mul.rn.f32x2 %0, %1, %2;" : "=l"(d) : "l"(a), "l"(b)); return d;
}
static __device__ __forceinline__ float tanh_approx(float x){
    float y; asm("tanh.approx.f32 %0, %1;" : "=f"(y) : "f"(x)); return y;
}

// ---------------- Hypernetwork: precompute (Wpairs, Upairs, B, -c) tables ----------------
// eval e -> seg = e/12, sub = (e%12)/3, stage = e%3 (0: t, 1: t+dt/2, 2: t+dt)
__global__ void hyper_kernel(const float* __restrict__ ts,
    const float* __restrict__ w1, const float* __restrict__ b1,
    const float* __restrict__ w2, const float* __restrict__ b2,
    const float* __restrict__ w3, const float* __restrict__ b3)
{
    __shared__ float h1s[64], h2s[64];
    const int e = blockIdx.x;
    const int tid = threadIdx.x;        // 128 threads
    const int seg = e / 12, r = e % 12, sub = r / 3, st = r % 3;

    float t0 = ts[seg], t1 = ts[seg+1];
    float dt = (t1 - t0) / 4.0f;
    float t = t0;
    for (int k = 0; k < sub; k++) t += dt;   // replicate reference's iterative t accumulation
    if      (st == 1) t += dt * 0.5f;
    else if (st == 2) t += dt;

    if (tid < 64) h1s[tid] = tanhf(w1[tid] * t + b1[tid]);
    __syncthreads();
    if (tid < 64) {
        float acc = b2[tid];
        const float* row = w2 + tid * 64;
        #pragma unroll 8
        for (int k = 0; k < 64; k++) acc += row[k] * h1s[k];
        h2s[tid] = tanhf(acc);
    }
    __syncthreads();

    const int i = tid;                  // output row 0..127
    float W[8], U[8];
    #pragma unroll
    for (int d = 0; d < 8; d++) {
        int mW = i*8 + d, mU = 1024 + i*8 + d, mG = 2048 + i*8 + d;
        float aw = b3[mW], au = b3[mU], ag = b3[mG];
        const float4* rw = (const float4*)(w3 + mW*64);
        const float4* ru = (const float4*)(w3 + mU*64);
        const float4* rg = (const float4*)(w3 + mG*64);
        #pragma unroll 4
        for (int k = 0; k < 16; k++) {
            float4 vw = rw[k], vu = ru[k], vg = rg[k];
            float hA = h2s[4*k], hB = h2s[4*k+1], hC = h2s[4*k+2], hD = h2s[4*k+3];
            aw += vw.x*hA + vw.y*hB + vw.z*hC + vw.w*hD;
            au += vu.x*hA + vu.y*hB + vu.z*hC + vu.w*hD;
            ag += vg.x*hA + vg.y*hB + vg.z*hC + vg.w*hD;
        }
        float sg = 1.0f / (1.0f + expf(-ag));
        W[d] = aw;
        U[d] = au * sg * (1.0f/128.0f);   // fold /WIDTH into U
    }
    int mB = 3072 + i;
    float ab = b3[mB];
    {
        const float4* rb = (const float4*)(w3 + mB*64);
        #pragma unroll 4
        for (int k = 0; k < 16; k++) {
            float4 v = rb[k];
            ab += v.x*h2s[4*k] + v.y*h2s[4*k+1] + v.z*h2s[4*k+2] + v.w*h2s[4*k+3];
        }
    }
    float c = 0.0f;                       // trace coefficient: sum_d W_d * (U_d/128)
    #pragma unroll
    for (int d = 0; d < 8; d++) c += W[d]*U[d];

    float* o = g_tab + (size_t)e*TABF + i*ROWF;
    #pragma unroll
    for (int d = 0; d < 8; d++) { o[d] = W[d]; o[8+d] = U[d]; }
    o[16] = ab; o[17] = 0.0f; o[18] = -c; o[19] = -c;
}

// ---------------- RHS: 2 samples per thread, d-packed f32x2 ----------------
// z[0..3] = sample A d-pairs (d01,d23,d45,d67), z[4..7] = sample B.
// tr accumulates (trace_A, trace_B) as a pair.
static __device__ __forceinline__ void rhs_eval(const float* __restrict__ tab,
                                                const u64 z[8], u64 dz[8], u64& tr)
{
    #pragma unroll
    for (int d = 0; d < 8; d++) dz[d] = 0ULL;
    tr = 0ULL;

    #pragma unroll 4
    for (int i = 0; i < NROW; i++) {
        const ulonglong2* r = (const ulonglong2*)(tab + i*ROWF);
        ulonglong2 w0 = r[0], w1 = r[1];   // W pairs: (W0,W1),(W2,W3) | (W4,W5),(W6,W7)
        ulonglong2 u0 = r[2], u1 = r[3];   // U pairs
        ulonglong2 bc = r[4];              // (B, 0) | (-c, -c)

        // sample A dot: s = sum_d W_d z_d + B
        u64 sa = ffma2(w0.x, z[0], bc.x);
        u64 sb = fmul2(w1.x, z[2]);
        sa = ffma2(w0.y, z[1], sa);
        sb = ffma2(w1.y, z[3], sb);
        sa = fadd2(sa, sb);
        float ax, ay; upk2(sa, ax, ay);
        float hA = tanh_approx(ax + ay);

        // sample B dot
        u64 ta = ffma2(w0.x, z[4], bc.x);
        u64 tb = fmul2(w1.x, z[6]);
        ta = ffma2(w0.y, z[5], ta);
        tb = ffma2(w1.y, z[7], tb);
        ta = fadd2(ta, tb);
        float bx, by; upk2(ta, bx, by);
        float hB = tanh_approx(bx + by);

        u64 hA2 = pk2(hA, hA), hB2 = pk2(hB, hB);
        dz[0] = ffma2(hA2, u0.x, dz[0]);
        dz[1] = ffma2(hA2, u0.y, dz[1]);
        dz[2] = ffma2(hA2, u1.x, dz[2]);
        dz[3] = ffma2(hA2, u1.y, dz[3]);
        dz[4] = ffma2(hB2, u0.x, dz[4]);
        dz[5] = ffma2(hB2, u0.y, dz[5]);
        dz[6] = ffma2(hB2, u1.x, dz[6]);
        dz[7] = ffma2(hB2, u1.y, dz[7]);

        float gA = fmaf(hA, hA, -1.0f);           // h^2 - 1
        float gB = fmaf(hB, hB, -1.0f);
        tr = ffma2(pk2(gA, gB), bc.y, tr);        // += (1-h^2)*c  (trace, per-sample lanes)
    }
}

// ---------------- Main integration kernel: 2 samples per thread ----------------
__global__ void __launch_bounds__(128) cnf_main(
    const float* __restrict__ ts, const float* __restrict__ z0,
    const float* __restrict__ lp0, float* __restrict__ out)
{
    __shared__ float stab[2*TABF];          // 20 KB: [E | M] staged tables
    float* sE = stab;
    float* sM = stab + TABF;
    const int tid = threadIdx.x;
    const int n0 = (blockIdx.x * 128 + tid) * 2;

    // load z for samples n0 (A), n0+1 (B); pack adjacent dims: z[k] = (z_{2k}, z_{2k+1})
    const float4* zv = (const float4*)(z0 + (size_t)n0*8);
    float4 p0 = zv[0], p1 = zv[1], p2 = zv[2], p3 = zv[3];
    u64 z[8];
    z[0]=pk2(p0.x,p0.y); z[1]=pk2(p0.z,p0.w); z[2]=pk2(p1.x,p1.y); z[3]=pk2(p1.z,p1.w);
    z[4]=pk2(p2.x,p2.y); z[5]=pk2(p2.z,p2.w); z[6]=pk2(p3.x,p3.y); z[7]=pk2(p3.z,p3.w);

    float lpa = lp0[n0], lpb = lp0[n0+1];
    u64 lp = pk2(lpa, lpb);

    // t = ts[0] output slice
    {
        float4* ov = (float4*)(out + (size_t)n0*8);
        ov[0]=p0; ov[1]=p1; ov[2]=p2; ov[3]=p3;
        out[LPOFF + n0]     = lpa;
        out[LPOFF + n0 + 1] = lpb;
    }

    const u64 M_TWO = pk2(2.0f, 2.0f);

    for (int seg = 0; seg < NSEG; seg++) {
        float t0 = ts[seg], t1 = ts[seg+1];
        float dt  = (t1 - t0) / 4.0f;
        float hdt = dt * 0.5f;
        float dt6 = dt / 6.0f;
        u64 DT = pk2(dt,dt), HDT = pk2(hdt,hdt), DT6 = pk2(dt6,dt6), NDT6 = pk2(-dt6,-dt6);

        for (int sub = 0; sub < NSUBS; sub++) {
            const int ev = (seg*NSUBS + sub)*3;

            // stage E <- stage0 table, M <- stage1 (midpoint) table
            __syncthreads();
            {
                const float4* srcE = (const float4*)(g_tab + (size_t)ev*TABF);
                const float4* srcM = (const float4*)(g_tab + (size_t)(ev+1)*TABF);
                float4* dE = (float4*)sE; float4* dM = (float4*)sM;
                #pragma unroll
                for (int j = tid; j < TABF/4; j += 128) { dE[j] = srcE[j]; dM[j] = srcM[j]; }
            }
            __syncthreads();

            u64 kd[8], acc[8], zt[8], tr, trs;

            rhs_eval(sE, z, kd, tr);                     // k1 @ t
            trs = tr;
            #pragma unroll
            for (int d = 0; d < 8; d++) { acc[d] = kd[d]; zt[d] = ffma2(HDT, kd[d], z[d]); }

            rhs_eval(sM, zt, kd, tr);                    // k2 @ t+dt/2
            trs = ffma2(M_TWO, tr, trs);
            #pragma unroll
            for (int d = 0; d < 8; d++) { acc[d] = ffma2(M_TWO, kd[d], acc[d]); zt[d] = ffma2(HDT, kd[d], z[d]); }

            rhs_eval(sM, zt, kd, tr);                    // k3 @ t+dt/2
            trs = ffma2(M_TWO, tr, trs);
            #pragma unroll
            for (int d = 0; d < 8; d++) { acc[d] = ffma2(M_TWO, kd[d], acc[d]); zt[d] = ffma2(DT, kd[d], z[d]); }

            // restage E <- stage2 (t+dt) table for k4
            __syncthreads();
            {
                const float4* srcE = (const float4*)(g_tab + (size_t)(ev+2)*TABF);
                float4* dE = (float4*)sE;
                #pragma unroll
                for (int j = tid; j < TABF/4; j += 128) dE[j] = srcE[j];
            }
            __syncthreads();

            rhs_eval(sE, zt, kd, tr);                    // k4 @ t+dt
            trs = fadd2(trs, tr);
            #pragma unroll
            for (int d = 0; d < 8; d++) { acc[d] = fadd2(acc[d], kd[d]); z[d] = ffma2(DT6, acc[d], z[d]); }
            lp = ffma2(NDT6, trs, lp);                   // lp += dt/6 * (-(tr1+2tr2+2tr3+tr4))
        }

        // write slice seg+1
        float q[16];
        upk2(z[0], q[0],  q[1]);  upk2(z[1], q[2],  q[3]);
        upk2(z[2], q[4],  q[5]);  upk2(z[3], q[6],  q[7]);
        upk2(z[4], q[8],  q[9]);  upk2(z[5], q[10], q[11]);
        upk2(z[6], q[12], q[13]); upk2(z[7], q[14], q[15]);
        float4* ov = (float4*)(out + (size_t)(seg+1)*NPTS*8 + (size_t)n0*8);
        ov[0] = make_float4(q[0],  q[1],  q[2],  q[3]);
        ov[1] = make_float4(q[4],  q[5],  q[6],  q[7]);
        ov[2] = make_float4(q[8],  q[9],  q[10], q[11]);
        ov[3] = make_float4(q[12], q[13], q[14], q[15]);
        float la, lb; upk2(lp, la, lb);
        out[LPOFF + (size_t)(seg+1)*NPTS + n0]     = la;
        out[LPOFF + (size_t)(seg+1)*NPTS + n0 + 1] = lb;
    }
}

extern "C" void kernel_launch(void* const* d_in, const int* in_sizes, int n_in,
                              void* d_out, int out_size) {
    const float* ts  = (const float*)d_in[0];
    const float* z0  = (const float*)d_in[1];
    const float* lp0 = (const float*)d_in[2];
    const float* w1  = (const float*)d_in[3];
    const float* b1  = (const float*)d_in[4];
    const float* w2  = (const float*)d_in[5];
    const float* b2  = (const float*)d_in[6];
    const float* w3  = (const float*)d_in[7];
    const float* b3  = (const float*)d_in[8];
    float* out = (float*)d_out;

    hyper_kernel<<<NEVAL, 128>>>(ts, w1, b1, w2, b2, w3, b3);
    cnf_main<<<NPTS/256, 128>>>(ts, z0, lp0, out);
}

// round 9
// speedup vs baseline: 1.3562x; 1.0929x over previous
#include <cuda_runtime.h>

// Problem constants
#define NSEG   7
#define NSUBS  4
#define NEVAL  (NSEG*NSUBS*3)   // 84 hypernet evaluations (seg, sub, stage)
#define NROW   128              // WIDTH
#define HROW   64               // rows per warp-group half
#define ROWF   20               // floats per table row: Wpair[8], Upair[8], B, 0, -c, -c
#define TABF   (NROW*ROWF)      // 2560 floats = 10KB per table
#define NPTS   65536
#define LPOFF  (8*NPTS*8)       // zt occupies first 8*N*8 floats, then logp 8*N
#define REDN   (9*128)          // reduction slots per buffer (u64 units)

__device__ float g_tab[NEVAL * TABF];   // 860 KB precomputed hypernet tables

typedef unsigned long long u64;

// ---------------- f32x2 packed helpers ----------------
static __device__ __forceinline__ u64 pk2(float a, float b){
    u64 r; asm("mov.b64 %0, {%1, %2};" : "=l"(r) : "f"(a), "f"(b)); return r;
}
static __device__ __forceinline__ void upk2(u64 v, float& a, float& b){
    asm("mov.b64 {%0, %1}, %2;" : "=f"(a), "=f"(b) : "l"(v));
}
static __device__ __forceinline__ u64 ffma2(u64 a, u64 b, u64 c){
    u64 d; asm("fma.rn.f32x2 %0, %1, %2, %3;" : "=l"(d) : "l"(a), "l"(b), "l"(c)); return d;
}
static __device__ __forceinline__ u64 fadd2(u64 a, u64 b){
    u64 d; asm("add.rn.f32x2 %0, %1, %2;" : "=l"(d) : "l"(a), "l"(b)); return d;
}
static __device__ __forceinline__ u64 fmul2(u64 a, u64 b){
    u64 d; asm("mul.rn.f32x2 %0, %1, %2;" : "=l"(d) : "l"(a), "l"(b)); return d;
}
static __device__ __forceinline__ float tanh_approx(float x){
    float y; asm("tanh.approx.f32 %0, %1;" : "=f"(y) : "f"(x)); return y;
}

// ---------------- Hypernetwork: precompute (Wpairs, Upairs, B, -c) tables ----------------
// eval e -> seg = e/12, sub = (e%12)/3, stage = e%3 (0: t, 1: t+dt/2, 2: t+dt)
__global__ void hyper_kernel(const float* __restrict__ ts,
    const float* __restrict__ w1, const float* __restrict__ b1,
    const float* __restrict__ w2, const float* __restrict__ b2,
    const float* __restrict__ w3, const float* __restrict__ b3)
{
    __shared__ float h1s[64], h2s[64];
    const int e = blockIdx.x;
    const int tid = threadIdx.x;        // 128 threads
    const int seg = e / 12, r = e % 12, sub = r / 3, st = r % 3;

    float t0 = ts[seg], t1 = ts[seg+1];
    float dt = (t1 - t0) / 4.0f;
    float t = t0;
    for (int k = 0; k < sub; k++) t += dt;   // replicate reference's iterative t accumulation
    if      (st == 1) t += dt * 0.5f;
    else if (st == 2) t += dt;

    if (tid < 64) h1s[tid] = tanhf(w1[tid] * t + b1[tid]);
    __syncthreads();
    if (tid < 64) {
        float acc = b2[tid];
        const float* row = w2 + tid * 64;
        #pragma unroll 8
        for (int k = 0; k < 64; k++) acc += row[k] * h1s[k];
        h2s[tid] = tanhf(acc);
    }
    __syncthreads();

    const int i = tid;                  // output row 0..127
    float W[8], U[8];
    #pragma unroll
    for (int d = 0; d < 8; d++) {
        int mW = i*8 + d, mU = 1024 + i*8 + d, mG = 2048 + i*8 + d;
        float aw = b3[mW], au = b3[mU], ag = b3[mG];
        const float4* rw = (const float4*)(w3 + mW*64);
        const float4* ru = (const float4*)(w3 + mU*64);
        const float4* rg = (const float4*)(w3 + mG*64);
        #pragma unroll 4
        for (int k = 0; k < 16; k++) {
            float4 vw = rw[k], vu = ru[k], vg = rg[k];
            float hA = h2s[4*k], hB = h2s[4*k+1], hC = h2s[4*k+2], hD = h2s[4*k+3];
            aw += vw.x*hA + vw.y*hB + vw.z*hC + vw.w*hD;
            au += vu.x*hA + vu.y*hB + vu.z*hC + vu.w*hD;
            ag += vg.x*hA + vg.y*hB + vg.z*hC + vg.w*hD;
        }
        float sg = 1.0f / (1.0f + expf(-ag));
        W[d] = aw;
        U[d] = au * sg * (1.0f/128.0f);   // fold /WIDTH into U
    }
    int mB = 3072 + i;
    float ab = b3[mB];
    {
        const float4* rb = (const float4*)(w3 + mB*64);
        #pragma unroll 4
        for (int k = 0; k < 16; k++) {
            float4 v = rb[k];
            ab += v.x*h2s[4*k] + v.y*h2s[4*k+1] + v.z*h2s[4*k+2] + v.w*h2s[4*k+3];
        }
    }
    float c = 0.0f;                       // trace coefficient: sum_d W_d * (U_d/128)
    #pragma unroll
    for (int d = 0; d < 8; d++) c += W[d]*U[d];

    float* o = g_tab + (size_t)e*TABF + i*ROWF;
    #pragma unroll
    for (int d = 0; d < 8; d++) { o[d] = W[d]; o[8+d] = U[d]; }
    o[16] = ab; o[17] = 0.0f; o[18] = -c; o[19] = -c;
}

// ---------------- RHS partial: 2 samples per thread, HROW rows ----------------
// z[0..3] = sample A d-pairs (d01,d23,d45,d67), z[4..7] = sample B.
// tab is pre-offset to this thread's row range.
static __device__ __forceinline__ void rhs_partial(const float* __restrict__ tab,
                                                   const u64 z[8], u64 dz[8], u64& tr)
{
    #pragma unroll
    for (int d = 0; d < 8; d++) dz[d] = 0ULL;
    tr = 0ULL;

    #pragma unroll 4
    for (int i = 0; i < HROW; i++) {
        const ulonglong2* r = (const ulonglong2*)(tab + i*ROWF);
        ulonglong2 w0 = r[0], w1 = r[1];   // W pairs
        ulonglong2 u0 = r[2], u1 = r[3];   // U pairs
        ulonglong2 bc = r[4];              // (B, 0) | (-c, -c)

        // sample A dot: s = sum_d W_d z_d + B
        u64 sa = ffma2(w0.x, z[0], bc.x);
        u64 sb = fmul2(w1.x, z[2]);
        sa = ffma2(w0.y, z[1], sa);
        sb = ffma2(w1.y, z[3], sb);
        sa = fadd2(sa, sb);
        float ax, ay; upk2(sa, ax, ay);
        float hA = tanh_approx(ax + ay);

        // sample B dot
        u64 ta = ffma2(w0.x, z[4], bc.x);
        u64 tb = fmul2(w1.x, z[6]);
        ta = ffma2(w0.y, z[5], ta);
        tb = ffma2(w1.y, z[7], tb);
        ta = fadd2(ta, tb);
        float bx, by; upk2(ta, bx, by);
        float hB = tanh_approx(bx + by);

        u64 hA2 = pk2(hA, hA), hB2 = pk2(hB, hB);
        dz[0] = ffma2(hA2, u0.x, dz[0]);
        dz[1] = ffma2(hA2, u0.y, dz[1]);
        dz[2] = ffma2(hA2, u1.x, dz[2]);
        dz[3] = ffma2(hA2, u1.y, dz[3]);
        dz[4] = ffma2(hB2, u0.x, dz[4]);
        dz[5] = ffma2(hB2, u0.y, dz[5]);
        dz[6] = ffma2(hB2, u1.x, dz[6]);
        dz[7] = ffma2(hB2, u1.y, dz[7]);

        float gA = fmaf(hA, hA, -1.0f);           // h^2 - 1
        float gB = fmaf(hB, hB, -1.0f);
        tr = ffma2(pk2(gA, gB), bc.y, tr);        // += (1-h^2)*c  (trace, per-sample lanes)
    }
}

// ---------------- Main integration kernel ----------------
// Threads tid and tid^64 cooperate on the SAME 2 samples: tid<64 does rows
// [0,64), tid>=64 does rows [64,128). Partials reduced via double-buffered smem.
__global__ void __launch_bounds__(128) cnf_main(
    const float* __restrict__ ts, const float* __restrict__ z0,
    const float* __restrict__ lp0, float* __restrict__ out)
{
    __shared__ float stab[2*TABF];          // 20 KB: [E | M] staged tables
    __shared__ u64 red[2*REDN];             // 18 KB: double-buffered partials
    float* sE = stab;
    float* sM = stab + TABF;
    const int tid  = threadIdx.x;
    const int half = tid >> 6;              // which row half this thread computes
    const int li   = tid & 63;
    const int n0   = (blockIdx.x * 64 + li) * 2;
    const int rb   = half * HROW * ROWF;    // table row-base offset (floats)
    const int pt   = tid ^ 64;              // partner thread
    int buf = 0;

    // load z for samples n0 (A), n0+1 (B); pack adjacent dims: z[k] = (z_{2k}, z_{2k+1})
    const float4* zv = (const float4*)(z0 + (size_t)n0*8);
    float4 p0 = zv[0], p1 = zv[1], p2 = zv[2], p3 = zv[3];
    u64 z[8];
    z[0]=pk2(p0.x,p0.y); z[1]=pk2(p0.z,p0.w); z[2]=pk2(p1.x,p1.y); z[3]=pk2(p1.z,p1.w);
    z[4]=pk2(p2.x,p2.y); z[5]=pk2(p2.z,p2.w); z[6]=pk2(p3.x,p3.y); z[7]=pk2(p3.z,p3.w);

    float lpa = lp0[n0], lpb = lp0[n0+1];
    u64 lp = pk2(lpa, lpb);

    // t = ts[0] output slice (half 0 only)
    if (half == 0) {
        float4* ov = (float4*)(out + (size_t)n0*8);
        ov[0]=p0; ov[1]=p1; ov[2]=p2; ov[3]=p3;
        out[LPOFF + n0]     = lpa;
        out[LPOFF + n0 + 1] = lpb;
    }

    const u64 M_TWO = pk2(2.0f, 2.0f);

    for (int seg = 0; seg < NSEG; seg++) {
        float t0 = ts[seg], t1 = ts[seg+1];
        float dt  = (t1 - t0) / 4.0f;
        float hdt = dt * 0.5f;
        float dt6 = dt / 6.0f;
        u64 DT = pk2(dt,dt), HDT = pk2(hdt,hdt), DT6 = pk2(dt6,dt6), NDT6 = pk2(-dt6,-dt6);

        for (int sub = 0; sub < NSUBS; sub++) {
            const int ev = (seg*NSUBS + sub)*3;

            // stage E <- stage0 table, M <- stage1 (midpoint) table.
            // (previous RHS's reduction barrier guarantees all prior sE/sM reads done)
            {
                const float4* srcE = (const float4*)(g_tab + (size_t)ev*TABF);
                const float4* srcM = (const float4*)(g_tab + (size_t)(ev+1)*TABF);
                float4* dE = (float4*)sE; float4* dM = (float4*)sM;
                #pragma unroll
                for (int j = tid; j < TABF/4; j += 128) { dE[j] = srcE[j]; dM[j] = srcM[j]; }
            }
            __syncthreads();

            u64 kd[8], acc[8], zt[8], tr, trs;

            // ---- k1 @ t ----
            rhs_partial(sE + rb, z, kd, tr);
            {   u64* wr = red + buf*REDN;
                #pragma unroll
                for (int d = 0; d < 8; d++) wr[d*128 + tid] = kd[d];
                wr[8*128 + tid] = tr;
                __syncthreads();
                #pragma unroll
                for (int d = 0; d < 8; d++) kd[d] = fadd2(kd[d], wr[d*128 + pt]);
                tr = fadd2(tr, wr[8*128 + pt]);
                buf ^= 1; }
            trs = tr;
            #pragma unroll
            for (int d = 0; d < 8; d++) { acc[d] = kd[d]; zt[d] = ffma2(HDT, kd[d], z[d]); }

            // ---- k2 @ t+dt/2 ----
            rhs_partial(sM + rb, zt, kd, tr);
            {   u64* wr = red + buf*REDN;
                #pragma unroll
                for (int d = 0; d < 8; d++) wr[d*128 + tid] = kd[d];
                wr[8*128 + tid] = tr;
                __syncthreads();
                #pragma unroll
                for (int d = 0; d < 8; d++) kd[d] = fadd2(kd[d], wr[d*128 + pt]);
                tr = fadd2(tr, wr[8*128 + pt]);
                buf ^= 1; }
            trs = ffma2(M_TWO, tr, trs);
            #pragma unroll
            for (int d = 0; d < 8; d++) { acc[d] = ffma2(M_TWO, kd[d], acc[d]); zt[d] = ffma2(HDT, kd[d], z[d]); }

            // ---- k3 @ t+dt/2 ----
            rhs_partial(sM + rb, zt, kd, tr);
            {   u64* wr = red + buf*REDN;
                #pragma unroll
                for (int d = 0; d < 8; d++) wr[d*128 + tid] = kd[d];
                wr[8*128 + tid] = tr;
                __syncthreads();
                #pragma unroll
                for (int d = 0; d < 8; d++) kd[d] = fadd2(kd[d], wr[d*128 + pt]);
                tr = fadd2(tr, wr[8*128 + pt]);
                buf ^= 1; }
            trs = ffma2(M_TWO, tr, trs);
            #pragma unroll
            for (int d = 0; d < 8; d++) { acc[d] = ffma2(M_TWO, kd[d], acc[d]); zt[d] = ffma2(DT, kd[d], z[d]); }

            // restage E <- stage2 (t+dt) table for k4 (k1 reads of sE long done)
            {
                const float4* srcE = (const float4*)(g_tab + (size_t)(ev+2)*TABF);
                float4* dE = (float4*)sE;
                #pragma unroll
                for (int j = tid; j < TABF/4; j += 128) dE[j] = srcE[j];
            }
            __syncthreads();

            // ---- k4 @ t+dt ----
            rhs_partial(sE + rb, zt, kd, tr);
            {   u64* wr = red + buf*REDN;
                #pragma unroll
                for (int d = 0; d < 8; d++) wr[d*128 + tid] = kd[d];
                wr[8*128 + tid] = tr;
                __syncthreads();
                #pragma unroll
                for (int d = 0; d < 8; d++) kd[d] = fadd2(kd[d], wr[d*128 + pt]);
                tr = fadd2(tr, wr[8*128 + pt]);
                buf ^= 1; }
            trs = fadd2(trs, tr);
            #pragma unroll
            for (int d = 0; d < 8; d++) { acc[d] = fadd2(acc[d], kd[d]); z[d] = ffma2(DT6, acc[d], z[d]); }
            lp = ffma2(NDT6, trs, lp);                   // lp += dt/6 * (-(tr1+2tr2+2tr3+tr4))
        }

        // write slice seg+1 (half 0 only; both halves hold identical state)
        if (half == 0) {
            float q[16];
            upk2(z[0], q[0],  q[1]);  upk2(z[1], q[2],  q[3]);
            upk2(z[2], q[4],  q[5]);  upk2(z[3], q[6],  q[7]);
            upk2(z[4], q[8],  q[9]);  upk2(z[5], q[10], q[11]);
            upk2(z[6], q[12], q[13]); upk2(z[7], q[14], q[15]);
            float4* ov = (float4*)(out + (size_t)(seg+1)*NPTS*8 + (size_t)n0*8);
            ov[0] = make_float4(q[0],  q[1],  q[2],  q[3]);
            ov[1] = make_float4(q[4],  q[5],  q[6],  q[7]);
            ov[2] = make_float4(q[8],  q[9],  q[10], q[11]);
            ov[3] = make_float4(q[12], q[13], q[14], q[15]);
            float la, lb; upk2(lp, la, lb);
            out[LPOFF + (size_t)(seg+1)*NPTS + n0]     = la;
            out[LPOFF + (size_t)(seg+1)*NPTS + n0 + 1] = lb;
        }
    }
}

extern "C" void kernel_launch(void* const* d_in, const int* in_sizes, int n_in,
                              void* d_out, int out_size) {
    const float* ts  = (const float*)d_in[0];
    const float* z0  = (const float*)d_in[1];
    const float* lp0 = (const float*)d_in[2];
    const float* w1  = (const float*)d_in[3];
    const float* b1  = (const float*)d_in[4];
    const float* w2  = (const float*)d_in[5];
    const float* b2  = (const float*)d_in[6];
    const float* w3  = (const float*)d_in[7];
    const float* b3  = (const float*)d_in[8];
    float* out = (float*)d_out;

    hyper_kernel<<<NEVAL, 128>>>(ts, w1, b1, w2, b2, w3, b3);
    cnf_main<<<NPTS/128, 128>>>(ts, z0, lp0, out);
}

// round 11
// speedup vs baseline: 1.3780x; 1.0160x over previous
#include <cuda_runtime.h>

// Problem constants
#define NSEG   7
#define NSUBS  4
#define NEVAL  (NSEG*NSUBS*3)   // 84 hypernet evaluations (seg, sub, stage)
#define NROW   128              // WIDTH
#define HROW   64               // rows per half
#define ROWF   20               // floats per table row: Wpair[8], Upair[8], B, 0, -c, -c
#define TABF   (NROW*ROWF)      // 2560 floats = 10KB per table
#define NPTS   65536
#define LPOFF  (8*NPTS*8)       // zt occupies first 8*N*8 floats, then logp 8*N

__device__ float g_tab[NEVAL * TABF];   // 860 KB precomputed hypernet tables

typedef unsigned long long u64;

// ---------------- f32x2 packed helpers ----------------
static __device__ __forceinline__ u64 pk2(float a, float b){
    u64 r; asm("mov.b64 %0, {%1, %2};" : "=l"(r) : "f"(a), "f"(b)); return r;
}
static __device__ __forceinline__ void upk2(u64 v, float& a, float& b){
    asm("mov.b64 {%0, %1}, %2;" : "=f"(a), "=f"(b) : "l"(v));
}
static __device__ __forceinline__ u64 ffma2(u64 a, u64 b, u64 c){
    u64 d; asm("fma.rn.f32x2 %0, %1, %2, %3;" : "=l"(d) : "l"(a), "l"(b), "l"(c)); return d;
}
static __device__ __forceinline__ u64 fadd2(u64 a, u64 b){
    u64 d; asm("add.rn.f32x2 %0, %1, %2;" : "=l"(d) : "l"(a), "l"(b)); return d;
}
static __device__ __forceinline__ u64 fmul2(u64 a, u64 b){
    u64 d; asm("mul.rn.f32x2 %0, %1, %2;" : "=l"(d) : "l"(a), "l"(b)); return d;
}
static __device__ __forceinline__ float tanh_approx(float x){
    float y; asm("tanh.approx.f32 %0, %1;" : "=f"(y) : "f"(x)); return y;
}
// partner-half reduce: add value from lane^16 (u64 payload)
static __device__ __forceinline__ u64 half_reduce(u64 v){
    u64 o = __shfl_xor_sync(0xffffffffu, v, 16);
    return fadd2(v, o);
}

// ---------------- Hypernetwork: precompute (Wpairs, Upairs, B, -c) tables ----------------
// eval e -> seg = e/12, sub = (e%12)/3, stage = e%3 (0: t, 1: t+dt/2, 2: t+dt)
__global__ void hyper_kernel(const float* __restrict__ ts,
    const float* __restrict__ w1, const float* __restrict__ b1,
    const float* __restrict__ w2, const float* __restrict__ b2,
    const float* __restrict__ w3, const float* __restrict__ b3)
{
    __shared__ float h1s[64], h2s[64];
    const int e = blockIdx.x;
    const int tid = threadIdx.x;        // 128 threads
    const int seg = e / 12, r = e % 12, sub = r / 3, st = r % 3;

    float t0 = ts[seg], t1 = ts[seg+1];
    float dt = (t1 - t0) / 4.0f;
    float t = t0;
    for (int k = 0; k < sub; k++) t += dt;   // replicate reference's iterative t accumulation
    if      (st == 1) t += dt * 0.5f;
    else if (st == 2) t += dt;

    if (tid < 64) h1s[tid] = tanhf(w1[tid] * t + b1[tid]);
    __syncthreads();
    if (tid < 64) {
        float acc = b2[tid];
        const float* row = w2 + tid * 64;
        #pragma unroll 8
        for (int k = 0; k < 64; k++) acc += row[k] * h1s[k];
        h2s[tid] = tanhf(acc);
    }
    __syncthreads();

    const int i = tid;                  // output row 0..127
    float W[8], U[8];
    #pragma unroll
    for (int d = 0; d < 8; d++) {
        int mW = i*8 + d, mU = 1024 + i*8 + d, mG = 2048 + i*8 + d;
        float aw = b3[mW], au = b3[mU], ag = b3[mG];
        const float4* rw = (const float4*)(w3 + mW*64);
        const float4* ru = (const float4*)(w3 + mU*64);
        const float4* rg = (const float4*)(w3 + mG*64);
        #pragma unroll 4
        for (int k = 0; k < 16; k++) {
            float4 vw = rw[k], vu = ru[k], vg = rg[k];
            float hA = h2s[4*k], hB = h2s[4*k+1], hC = h2s[4*k+2], hD = h2s[4*k+3];
            aw += vw.x*hA + vw.y*hB + vw.z*hC + vw.w*hD;
            au += vu.x*hA + vu.y*hB + vu.z*hC + vu.w*hD;
            ag += vg.x*hA + vg.y*hB + vg.z*hC + vg.w*hD;
        }
        float sg = 1.0f / (1.0f + expf(-ag));
        W[d] = aw;
        U[d] = au * sg * (1.0f/128.0f);   // fold /WIDTH into U
    }
    int mB = 3072 + i;
    float ab = b3[mB];
    {
        const float4* rb = (const float4*)(w3 + mB*64);
        #pragma unroll 4
        for (int k = 0; k < 16; k++) {
            float4 v = rb[k];
            ab += v.x*h2s[4*k] + v.y*h2s[4*k+1] + v.z*h2s[4*k+2] + v.w*h2s[4*k+3];
        }
    }
    float c = 0.0f;                       // trace coefficient: sum_d W_d * (U_d/128)
    #pragma unroll
    for (int d = 0; d < 8; d++) c += W[d]*U[d];

    float* o = g_tab + (size_t)e*TABF + i*ROWF;
    #pragma unroll
    for (int d = 0; d < 8; d++) { o[d] = W[d]; o[8+d] = U[d]; }
    o[16] = ab; o[17] = 0.0f; o[18] = -c; o[19] = -c;
}

// ---------------- RHS partial: 2 samples per thread, HROW rows ----------------
// z[0..3] = sample A d-pairs, z[4..7] = sample B. tab pre-offset to this
// lane-half's row range. Result is the partial over HROW rows.
static __device__ __forceinline__ void rhs_partial(const float* __restrict__ tab,
                                                   const u64 z[8], u64 dz[8], u64& tr)
{
    #pragma unroll
    for (int d = 0; d < 8; d++) dz[d] = 0ULL;
    tr = 0ULL;

    #pragma unroll 4
    for (int i = 0; i < HROW; i++) {
        const ulonglong2* r = (const ulonglong2*)(tab + i*ROWF);
        ulonglong2 w0 = r[0], w1 = r[1];   // W pairs
        ulonglong2 u0 = r[2], u1 = r[3];   // U pairs
        ulonglong2 bc = r[4];              // (B, 0) | (-c, -c)

        // sample A dot: s = sum_d W_d z_d + B
        u64 sa = ffma2(w0.x, z[0], bc.x);
        u64 sb = fmul2(w1.x, z[2]);
        sa = ffma2(w0.y, z[1], sa);
        sb = ffma2(w1.y, z[3], sb);
        sa = fadd2(sa, sb);
        float ax, ay; upk2(sa, ax, ay);
        float hA = tanh_approx(ax + ay);

        // sample B dot
        u64 ta = ffma2(w0.x, z[4], bc.x);
        u64 tb = fmul2(w1.x, z[6]);
        ta = ffma2(w0.y, z[5], ta);
        tb = ffma2(w1.y, z[7], tb);
        ta = fadd2(ta, tb);
        float bx, by; upk2(ta, bx, by);
        float hB = tanh_approx(bx + by);

        u64 hA2 = pk2(hA, hA), hB2 = pk2(hB, hB);
        dz[0] = ffma2(hA2, u0.x, dz[0]);
        dz[1] = ffma2(hA2, u0.y, dz[1]);
        dz[2] = ffma2(hA2, u1.x, dz[2]);
        dz[3] = ffma2(hA2, u1.y, dz[3]);
        dz[4] = ffma2(hB2, u0.x, dz[4]);
        dz[5] = ffma2(hB2, u0.y, dz[5]);
        dz[6] = ffma2(hB2, u1.x, dz[6]);
        dz[7] = ffma2(hB2, u1.y, dz[7]);

        float gA = fmaf(hA, hA, -1.0f);           // h^2 - 1
        float gB = fmaf(hB, hB, -1.0f);
        tr = ffma2(pk2(gA, gB), bc.y, tr);        // += (1-h^2)*c  (trace)
    }
}

// ---------------- Main integration kernel ----------------
// Lanes l and l^16 of the SAME warp cooperate on the same 2 samples:
// lanes 0-15 do rows [0,64), lanes 16-31 do rows [64,128).
// Partials reduced by a single shfl.xor(16) butterfly — no barriers, no smem.
__global__ void __launch_bounds__(128) cnf_main(
    const float* __restrict__ ts, const float* __restrict__ z0,
    const float* __restrict__ lp0, float* __restrict__ out)
{
    __shared__ float stab[3*TABF];          // 30 KB: [E0 | M | E2] staged tables
    float* s0 = stab;
    float* s1 = stab + TABF;
    float* s2 = stab + 2*TABF;
    const int tid  = threadIdx.x;
    const int lane = tid & 31;
    const int wrp  = tid >> 5;
    const int half = lane >> 4;             // which row half this lane computes
    const int li   = lane & 15;
    const int n0   = (blockIdx.x * 64 + wrp * 16 + li) * 2;
    const int rb   = half * HROW * ROWF;    // table row-base offset (floats)

    // load z for samples n0 (A), n0+1 (B); pack adjacent dims: z[k] = (z_{2k}, z_{2k+1})
    const float4* zv = (const float4*)(z0 + (size_t)n0*8);
    float4 p0 = zv[0], p1 = zv[1], p2 = zv[2], p3 = zv[3];
    u64 z[8];
    z[0]=pk2(p0.x,p0.y); z[1]=pk2(p0.z,p0.w); z[2]=pk2(p1.x,p1.y); z[3]=pk2(p1.z,p1.w);
    z[4]=pk2(p2.x,p2.y); z[5]=pk2(p2.z,p2.w); z[6]=pk2(p3.x,p3.y); z[7]=pk2(p3.z,p3.w);

    float lpa = lp0[n0], lpb = lp0[n0+1];
    u64 lp = pk2(lpa, lpb);

    // t = ts[0] output slice (half 0 only)
    if (half == 0) {
        float4* ov = (float4*)(out + (size_t)n0*8);
        ov[0]=p0; ov[1]=p1; ov[2]=p2; ov[3]=p3;
        out[LPOFF + n0]     = lpa;
        out[LPOFF + n0 + 1] = lpb;
    }

    const u64 M_TWO = pk2(2.0f, 2.0f);

    for (int seg = 0; seg < NSEG; seg++) {
        float t0 = ts[seg], t1 = ts[seg+1];
        float dt  = (t1 - t0) / 4.0f;
        float hdt = dt * 0.5f;
        float dt6 = dt / 6.0f;
        u64 DT = pk2(dt,dt), HDT = pk2(hdt,hdt), DT6 = pk2(dt6,dt6), NDT6 = pk2(-dt6,-dt6);

        for (int sub = 0; sub < NSUBS; sub++) {
            const int ev = (seg*NSUBS + sub)*3;

            // stage all 3 tables for this substep: E0 (k1), M (k2,k3), E2 (k4)
            __syncthreads();                      // protect prior substep's reads
            {
                const float4* src = (const float4*)(g_tab + (size_t)ev*TABF);
                float4* dst = (float4*)stab;
                #pragma unroll
                for (int j = tid; j < 3*TABF/4; j += 128) dst[j] = src[j];
            }
            __syncthreads();

            u64 kd[8], acc[8], zt[8], tr, trs;

            // ---- k1 @ t ----
            rhs_partial(s0 + rb, z, kd, tr);
            #pragma unroll
            for (int d = 0; d < 8; d++) kd[d] = half_reduce(kd[d]);
            tr = half_reduce(tr);
            trs = tr;
            #pragma unroll
            for (int d = 0; d < 8; d++) { acc[d] = kd[d]; zt[d] = ffma2(HDT, kd[d], z[d]); }

            // ---- k2 @ t+dt/2 ----
            rhs_partial(s1 + rb, zt, kd, tr);
            #pragma unroll
            for (int d = 0; d < 8; d++) kd[d] = half_reduce(kd[d]);
            tr = half_reduce(tr);
            trs = ffma2(M_TWO, tr, trs);
            #pragma unroll
            for (int d = 0; d < 8; d++) { acc[d] = ffma2(M_TWO, kd[d], acc[d]); zt[d] = ffma2(HDT, kd[d], z[d]); }

            // ---- k3 @ t+dt/2 ----
            rhs_partial(s1 + rb, zt, kd, tr);
            #pragma unroll
            for (int d = 0; d < 8; d++) kd[d] = half_reduce(kd[d]);
            tr = half_reduce(tr);
            trs = ffma2(M_TWO, tr, trs);
            #pragma unroll
            for (int d = 0; d < 8; d++) { acc[d] = ffma2(M_TWO, kd[d], acc[d]); zt[d] = ffma2(DT, kd[d], z[d]); }

            // ---- k4 @ t+dt ----
            rhs_partial(s2 + rb, zt, kd, tr);
            #pragma unroll
            for (int d = 0; d < 8; d++) kd[d] = half_reduce(kd[d]);
            tr = half_reduce(tr);
            trs = fadd2(trs, tr);
            #pragma unroll
            for (int d = 0; d < 8; d++) { acc[d] = fadd2(acc[d], kd[d]); z[d] = ffma2(DT6, acc[d], z[d]); }
            lp = ffma2(NDT6, trs, lp);                   // lp += dt/6 * (-(tr1+2tr2+2tr3+tr4))
        }

        // write slice seg+1 (half 0 only; both halves hold identical state)
        if (half == 0) {
            float q[16];
            upk2(z[0], q[0],  q[1]);  upk2(z[1], q[2],  q[3]);
            upk2(z[2], q[4],  q[5]);  upk2(z[3], q[6],  q[7]);
            upk2(z[4], q[8],  q[9]);  upk2(z[5], q[10], q[11]);
            upk2(z[6], q[12], q[13]); upk2(z[7], q[14], q[15]);
            float4* ov = (float4*)(out + (size_t)(seg+1)*NPTS*8 + (size_t)n0*8);
            ov[0] = make_float4(q[0],  q[1],  q[2],  q[3]);
            ov[1] = make_float4(q[4],  q[5],  q[6],  q[7]);
            ov[2] = make_float4(q[8],  q[9],  q[10], q[11]);
            ov[3] = make_float4(q[12], q[13], q[14], q[15]);
            float la, lb; upk2(lp, la, lb);
            out[LPOFF + (size_t)(seg+1)*NPTS + n0]     = la;
            out[LPOFF + (size_t)(seg+1)*NPTS + n0 + 1] = lb;
        }
    }
}

extern "C" void kernel_launch(void* const* d_in, const int* in_sizes, int n_in,
                              void* d_out, int out_size) {
    const float* ts  = (const float*)d_in[0];
    const float* z0  = (const float*)d_in[1];
    const float* lp0 = (const float*)d_in[2];
    const float* w1  = (const float*)d_in[3];
    const float* b1  = (const float*)d_in[4];
    const float* w2  = (const float*)d_in[5];
    const float* b2  = (const float*)d_in[6];
    const float* w3  = (const float*)d_in[7];
    const float* b3  = (const float*)d_in[8];
    float* out = (float*)d_out;

    hyper_kernel<<<NEVAL, 128>>>(ts, w1, b1, w2, b2, w3, b3);
    cnf_main<<<NPTS/128, 128>>>(ts, z0, lp0, out);
}